// round 11
// baseline (speedup 1.0000x reference)
#include <cuda_runtime.h>
#include <cuda_fp16.h>
#include <cstdint>

#define NB 64
#define S  512
#define NEG_MASK -999999.0f

#define TENS ((size_t)NB * S * S)

// ---------------- scratch ---------------------------------------------------
__device__ float  g_sim [TENS];
__device__ float  g_simT[TENS];
__device__ __half g_buf[6 * TENS];

#define PRE_HI  0
#define PRE_LO  1
#define HYP_HI  2
#define HYP_LO  3
#define ATT_A   4
#define ATT_BT  5

// ---------------- helpers ---------------------------------------------------
__device__ __forceinline__ uint32_t smem_to_u32(const void* p) {
    uint32_t a;
    asm("{ .reg .u64 t; cvta.to.shared.u64 t, %1; cvt.u32.u64 %0, t; }" : "=r"(a) : "l"(p));
    return a;
}
__device__ __forceinline__ void ldsm_x4(uint32_t* r, uint32_t addr) {
    asm volatile("ldmatrix.sync.aligned.m8n8.x4.shared.b16 {%0,%1,%2,%3}, [%4];"
                 : "=r"(r[0]), "=r"(r[1]), "=r"(r[2]), "=r"(r[3]) : "r"(addr));
}
__device__ __forceinline__ void ldsm_x4_trans(uint32_t* r, uint32_t addr) {
    asm volatile("ldmatrix.sync.aligned.m8n8.x4.trans.shared.b16 {%0,%1,%2,%3}, [%4];"
                 : "=r"(r[0]), "=r"(r[1]), "=r"(r[2]), "=r"(r[3]) : "r"(addr));
}
__device__ __forceinline__ void mma16816(float* c, const uint32_t* a, const uint32_t* b) {
    asm volatile(
        "mma.sync.aligned.m16n8k16.row.col.f32.f16.f16.f32 "
        "{%0,%1,%2,%3}, {%4,%5,%6,%7}, {%8,%9}, {%0,%1,%2,%3};"
        : "+f"(c[0]), "+f"(c[1]), "+f"(c[2]), "+f"(c[3])
        : "r"(a[0]), "r"(a[1]), "r"(a[2]), "r"(a[3]), "r"(b[0]), "r"(b[1]));
}
__device__ __forceinline__ uint32_t pack2(__half a, __half b) {
    __half2 h = __halves2half2(a, b);
    return *reinterpret_cast<uint32_t*>(&h);
}

// ---------------------------------------------------------------------------
// Element-wise hi/lo fp16 split of both inputs. grid (TENS/1024, 2), block 256.
// ---------------------------------------------------------------------------
__global__ __launch_bounds__(256)
void convert_split_kernel(const float4* __restrict__ X1,
                          uint2* __restrict__ hi1, uint2* __restrict__ lo1,
                          const float4* __restrict__ X2,
                          uint2* __restrict__ hi2, uint2* __restrict__ lo2)
{
    const float4* X = blockIdx.y ? X2 : X1;
    uint2* hi = blockIdx.y ? hi2 : hi1;
    uint2* lo = blockIdx.y ? lo2 : lo1;
    size_t i = (size_t)blockIdx.x * 256 + threadIdx.x;
    float4 v = X[i];
    __half h0 = __float2half_rn(v.x), h1 = __float2half_rn(v.y);
    __half h2 = __float2half_rn(v.z), h3 = __float2half_rn(v.w);
    uint2 H, L;
    H.x = pack2(h0, h1);
    H.y = pack2(h2, h3);
    L.x = pack2(__float2half_rn(v.x - __half2float(h0)),
                __float2half_rn(v.y - __half2float(h1)));
    L.y = pack2(__float2half_rn(v.z - __half2float(h2)),
                __float2half_rn(v.w - __half2float(h3)));
    hi[i] = H;
    lo[i] = L;
}

// ---------------------------------------------------------------------------
// fp16 tensor-core GEMM (mma.sync m16n8k16), fp32 out.
// 256 threads = 8 warps in 4x2 grid, 64x64 warp tile, CTA tile 256x128.
// NTERMS=3: BK=32, 3 stages (48KB/stage); C = Ahi*Bhi + Ahi*Blo + Alo*Bhi;
//           B K-major [n][k]; writes C + CT (CT via smem transpose).
// NTERMS=1: BK=32, 4 stages (24KB/stage); C = A*B; B row-major [k][n] via
//           ldmatrix.x4.trans; merged dual launch.
// 1 CTA/SM.
// ---------------------------------------------------------------------------
template<int NTERMS>
__global__ __launch_bounds__(256, 1)
void gemm_tc_kernel(const __half* __restrict__ Ahi, const __half* __restrict__ Alo,
                    const __half* __restrict__ Bhi, const __half* __restrict__ Blo,
                    float* __restrict__ C, float* __restrict__ CT,
                    const __half* __restrict__ A2, const __half* __restrict__ B2,
                    float* __restrict__ C2)
{
    constexpr int NSTAGES = (NTERMS == 3) ? 3 : 4;
    constexpr int STSZ    = (NTERMS == 3) ? 49152 : 24576;
    constexpr int NITER   = 16;

    extern __shared__ char smem[];
    const uint32_t sb = smem_to_u32(smem);
    const int tid = threadIdx.x;
    const int lane = tid & 31, wid = tid >> 5;
    const int wm = wid >> 1;            // 0..3 (64 m-rows each, 256 total)
    const int wn = wid & 1;             // 0..1 (64 n-cols each, 128 total)
    const int zb = blockIdx.z;
    const size_t boff = (size_t)(zb & (NB - 1)) * S * S;
    const int m0 = blockIdx.y * 256, n0 = blockIdx.x * 128;

    const __half *gAhi, *gAlo, *gBhi, *gBlo, *gBkn;
    float* Cout;
    if (NTERMS == 3) {
        gAhi = Ahi + boff + (size_t)m0 * S;
        gAlo = Alo + boff + (size_t)m0 * S;
        gBhi = Bhi + boff + (size_t)n0 * S;
        gBlo = Blo + boff + (size_t)n0 * S;
        Cout = C;
    } else {
        if (zb < NB) { gAhi = Ahi + boff + (size_t)m0 * S; gBkn = Bhi + boff + n0; Cout = C; }
        else         { gAhi = A2  + boff + (size_t)m0 * S; gBkn = B2  + boff + n0; Cout = C2; }
    }

    auto load_stage = [&](int st, int k0) {
        uint32_t base = sb + st * STSZ;
        if (NTERMS == 3) {
            // Ahi/Alo: [256 m][32 k], 64B rows, 16KB each
#pragma unroll
            for (int t = 0; t < 2; t++) {
                const __half* g = (t == 0 ? gAhi : gAlo) + k0;
                uint32_t tb = base + t * 16384;
#pragma unroll
                for (int j = 0; j < 4; j++) {
                    int idx = j * 256 + tid;
                    int row = idx >> 2, c = idx & 3;
                    uint32_t dst = tb + row * 64 + ((uint32_t)(c ^ ((row >> 1) & 3)) << 4);
                    asm volatile("cp.async.cg.shared.global [%0], [%1], 16;"
                                 :: "r"(dst), "l"(g + row * S + c * 8) : "memory");
                }
            }
            // Bhi/Blo: [128 n][32 k], 64B rows, 8KB each
#pragma unroll
            for (int t = 0; t < 2; t++) {
                const __half* g = (t == 0 ? gBhi : gBlo) + k0;
                uint32_t tb = base + 32768 + t * 8192;
#pragma unroll
                for (int j = 0; j < 2; j++) {
                    int idx = j * 256 + tid;
                    int row = idx >> 2, c = idx & 3;
                    uint32_t dst = tb + row * 64 + ((uint32_t)(c ^ ((row >> 1) & 3)) << 4);
                    asm volatile("cp.async.cg.shared.global [%0], [%1], 16;"
                                 :: "r"(dst), "l"(g + row * S + c * 8) : "memory");
                }
            }
        } else {
            // A: [256 m][32 k], 64B rows, 16KB
#pragma unroll
            for (int j = 0; j < 4; j++) {
                int idx = j * 256 + tid;
                int row = idx >> 2, c = idx & 3;
                uint32_t dst = base + row * 64 + ((uint32_t)(c ^ ((row >> 1) & 3)) << 4);
                asm volatile("cp.async.cg.shared.global [%0], [%1], 16;"
                             :: "r"(dst), "l"(gAhi + row * S + k0 + c * 8) : "memory");
            }
            // B: [32 k][128 n], 256B rows, 8KB
#pragma unroll
            for (int j = 0; j < 2; j++) {
                int idx = j * 256 + tid;
                int row = idx >> 4, c = idx & 15;
                uint32_t dst = base + 16384 + row * 256 + ((uint32_t)(c ^ (row & 7)) << 4);
                asm volatile("cp.async.cg.shared.global [%0], [%1], 16;"
                             :: "r"(dst), "l"(gBkn + (size_t)(k0 + row) * S + c * 8) : "memory");
            }
        }
        asm volatile("cp.async.commit_group;" ::: "memory");
    };

    float acc[4][8][4];
#pragma unroll
    for (int i = 0; i < 4; i++)
#pragma unroll
        for (int j = 0; j < 8; j++)
#pragma unroll
            for (int q = 0; q < 4; q++) acc[i][j][q] = 0.0f;

#pragma unroll
    for (int s = 0; s < NSTAGES - 1; s++) load_stage(s, s * 32);

    for (int i = 0; i < NITER; i++) {
        if (NSTAGES == 4) asm volatile("cp.async.wait_group 2;" ::: "memory");
        else              asm volatile("cp.async.wait_group 1;" ::: "memory");
        __syncthreads();
        if (i + NSTAGES - 1 < NITER)
            load_stage((i + NSTAGES - 1) % NSTAGES, (i + NSTAGES - 1) * 32);
        else
            asm volatile("cp.async.commit_group;" ::: "memory");

        const uint32_t stb = sb + (i % NSTAGES) * STSZ;
#pragma unroll
        for (int ks = 0; ks < 2; ks++) {
            uint32_t ah[4][4], al[4][4];
#pragma unroll
            for (int mf = 0; mf < 4; mf++) {
                int row = wm * 64 + mf * 16 + (lane & 15);
                int ch = (ks * 2 + (lane >> 4)) ^ ((row >> 1) & 3);
                uint32_t off = row * 64 + (ch << 4);
                ldsm_x4(ah[mf], stb + off);
                if (NTERMS == 3) ldsm_x4(al[mf], stb + 16384 + off);
            }
#pragma unroll
            for (int nfp = 0; nfp < 4; nfp++) {      // pairs of n8 groups
                uint32_t bh[4], bl[4];
                if (NTERMS == 3) {
                    int nrow = wn * 64 + nfp * 16 + ((lane >> 4) << 3) + (lane & 7);
                    int ch = (ks * 2 + ((lane >> 3) & 1)) ^ ((nrow >> 1) & 3);
                    uint32_t off = nrow * 64 + (ch << 4);
                    ldsm_x4(bh, stb + 32768 + off);
                    ldsm_x4(bl, stb + 40960 + off);
                } else {
                    int row = ks * 16 + ((lane >> 3) & 1) * 8 + (lane & 7);
                    int chunk = wn * 8 + nfp * 2 + (lane >> 4);
                    uint32_t off = row * 256 + ((uint32_t)(chunk ^ (row & 7)) << 4);
                    ldsm_x4_trans(bh, stb + 16384 + off);
                }
#pragma unroll
                for (int nn = 0; nn < 2; nn++) {
                    int nf = nfp * 2 + nn;
#pragma unroll
                    for (int mf = 0; mf < 4; mf++) {
                        mma16816(acc[mf][nf], ah[mf], bh + nn * 2);
                        if (NTERMS == 3) {
                            mma16816(acc[mf][nf], ah[mf], bl + nn * 2);
                            mma16816(acc[mf][nf], al[mf], bh + nn * 2);
                        }
                    }
                }
            }
        }
    }

    // ---- epilogue: direct C store (coalesced float2 rows) -----------------
    float* Cb = Cout + boff;
#pragma unroll
    for (int mf = 0; mf < 4; mf++) {
#pragma unroll
        for (int nf = 0; nf < 8; nf++) {
            int r  = m0 + wm * 64 + mf * 16 + (lane >> 2);
            int cc = n0 + wn * 64 + nf * 8 + (lane & 3) * 2;
            *(float2*)&Cb[(size_t)r * S + cc]       = make_float2(acc[mf][nf][0], acc[mf][nf][1]);
            *(float2*)&Cb[(size_t)(r + 8) * S + cc] = make_float2(acc[mf][nf][2], acc[mf][nf][3]);
        }
    }

    // ---- CT epilogue (NTERMS=3): transpose via smem, coalesced writes -----
    if (NTERMS == 3) {
        constexpr int PITCH = 264;                 // floats; 264*4B, 16B-aligned
        float* smT = (float*)smem;                 // 128*264*4 = 135KB <= 144KB
        __syncthreads();                           // pipeline smem reads all done
#pragma unroll
        for (int mf = 0; mf < 4; mf++)
#pragma unroll
            for (int nf = 0; nf < 8; nf++) {
                int rl  = wm * 64 + mf * 16 + (lane >> 2);
                int ccl = wn * 64 + nf * 8 + (lane & 3) * 2;
                smT[ccl * PITCH + rl]           = acc[mf][nf][0];
                smT[(ccl + 1) * PITCH + rl]     = acc[mf][nf][1];
                smT[ccl * PITCH + rl + 8]       = acc[mf][nf][2];
                smT[(ccl + 1) * PITCH + rl + 8] = acc[mf][nf][3];
            }
        __syncthreads();
        float* Tb = CT + boff;
#pragma unroll
        for (int r4 = 0; r4 < 8; r4++) {
            int ccl = wid * 16 + r4 * 2 + (lane >> 4);
#pragma unroll
            for (int cg = 0; cg < 4; cg++) {
                int c4 = (lane & 15) + cg * 16;
                float4 v = *(float4*)&smT[ccl * PITCH + c4 * 4];
                *(float4*)&Tb[(size_t)(n0 + ccl) * S + m0 + c4 * 4] = v;
            }
        }
    }
}

// ---------------------------------------------------------------------------
// Fused row softmax: z=0: sim rows + pre_mask -> attA [p][h]
//                    z=1: simT rows + hyp_mask -> attBT [h][p]
// One warp per row, shfl reductions. grid (S/8, NB, 2), block 256.
// ---------------------------------------------------------------------------
__global__ __launch_bounds__(256)
void softmax_fused_kernel(const int* __restrict__ pre_mask,
                          const int* __restrict__ hyp_mask,
                          __half* __restrict__ attA, __half* __restrict__ attBT)
{
    const int z = blockIdx.z;
    const float* src = z ? g_simT : g_sim;
    const int*  mask = z ? hyp_mask : pre_mask;
    __half*      dst = z ? attBT : attA;

    const int b = blockIdx.y;
    const int w = threadIdx.x >> 5, lane = threadIdx.x & 31;
    const int p = blockIdx.x * 8 + w;
    const float c = (mask[b * S + p] == 0) ? NEG_MASK : 0.0f;
    const size_t off = ((size_t)b * S + p) * S;
    const float* row = src + off;

    float4 v[4];
#pragma unroll
    for (int seg = 0; seg < 4; seg++) {
        v[seg] = *(const float4*)&row[seg * 128 + lane * 4];
        v[seg].x += c; v[seg].y += c; v[seg].z += c; v[seg].w += c;
    }

    float M = -3.0e38f;
#pragma unroll
    for (int seg = 0; seg < 4; seg++)
        M = fmaxf(M, fmaxf(fmaxf(v[seg].x, v[seg].y), fmaxf(v[seg].z, v[seg].w)));
#pragma unroll
    for (int o = 16; o > 0; o >>= 1)
        M = fmaxf(M, __shfl_xor_sync(0xFFFFFFFFu, M, o));

    float s = 0.0f;
    float4 e[4];
#pragma unroll
    for (int seg = 0; seg < 4; seg++) {
        e[seg].x = __expf(v[seg].x - M); e[seg].y = __expf(v[seg].y - M);
        e[seg].z = __expf(v[seg].z - M); e[seg].w = __expf(v[seg].w - M);
        s += e[seg].x + e[seg].y + e[seg].z + e[seg].w;
    }
#pragma unroll
    for (int o = 16; o > 0; o >>= 1)
        s += __shfl_xor_sync(0xFFFFFFFFu, s, o);
    const float inv = 1.0f / s;

#pragma unroll
    for (int seg = 0; seg < 4; seg++) {
        size_t o4 = off + seg * 128 + lane * 4;
        *(uint2*)&dst[o4] = make_uint2(
            pack2(__float2half_rn(e[seg].x * inv), __float2half_rn(e[seg].y * inv)),
            pack2(__float2half_rn(e[seg].z * inv), __float2half_rn(e[seg].w * inv)));
    }
}

// ---------------------------------------------------------------------------
extern "C" void kernel_launch(void* const* d_in, const int* in_sizes, int n_in,
                              void* d_out, int out_size)
{
    const float* premise  = (const float*)d_in[0];
    const int*   pre_mask = (const int*)  d_in[1];
    const float* hypo     = (const float*)d_in[2];
    const int*   hyp_mask = (const int*)  d_in[3];
    float* out1 = (float*)d_out;
    float* out2 = out1 + TENS;

    float *sim, *simT;
    __half* buf;
    cudaGetSymbolAddress((void**)&sim,  g_sim);
    cudaGetSymbolAddress((void**)&simT, g_simT);
    cudaGetSymbolAddress((void**)&buf,  g_buf);
    auto slot = [&](int i) { return buf + (size_t)i * TENS; };

    const int SMEM3 = 3 * 49152;   // 144 KB
    const int SMEM1 = 4 * 24576;   // 96 KB
    cudaFuncSetAttribute(gemm_tc_kernel<3>,
                         cudaFuncAttributeMaxDynamicSharedMemorySize, SMEM3);
    cudaFuncSetAttribute(gemm_tc_kernel<1>,
                         cudaFuncAttributeMaxDynamicSharedMemorySize, SMEM1);

    // 1. hi/lo fp16 splits of both inputs (element-wise, one launch)
    convert_split_kernel<<<dim3((unsigned)(TENS / 1024), 2), 256>>>(
        (const float4*)premise, (uint2*)slot(PRE_HI), (uint2*)slot(PRE_LO),
        (const float4*)hypo,    (uint2*)slot(HYP_HI), (uint2*)slot(HYP_LO));

    // 2. sim = premise @ hypothesis^T (3-term split) -> sim and simT
    gemm_tc_kernel<3><<<dim3(4, 2, NB), 256, SMEM3>>>(
        slot(PRE_HI), slot(PRE_LO), slot(HYP_HI), slot(HYP_LO), sim, simT,
        nullptr, nullptr, nullptr);

    // 3. both softmaxes in one launch -> attA [p][h], attBT [h][p]
    softmax_fused_kernel<<<dim3(S / 8, NB, 2), 256>>>(
        pre_mask, hyp_mask, slot(ATT_A), slot(ATT_BT));

    // 4+5. both attended GEMMs (256x128 tile, B row-major via ldmatrix.x4.trans)
    //      z<NB: attA @ hyp -> out1 ; z>=NB: attBT @ pre -> out2
    gemm_tc_kernel<1><<<dim3(4, 2, 2 * NB), 256, SMEM1>>>(
        slot(ATT_A), nullptr, slot(HYP_HI), nullptr, out1, nullptr,
        slot(ATT_BT), slot(PRE_HI), out2);
}

// round 12
// speedup vs baseline: 1.1848x; 1.1848x over previous
#include <cuda_runtime.h>
#include <cuda_fp16.h>
#include <cstdint>

#define NB 64
#define S  512
#define NEG_MASK -999999.0f

#define TENS ((size_t)NB * S * S)

// ---------------- scratch ---------------------------------------------------
__device__ float  g_sim [TENS];
__device__ float  g_simT[TENS];
__device__ __half g_buf[6 * TENS];

#define PRE_HI  0
#define PRE_LO  1
#define HYP_HI  2
#define HYP_LO  3
#define ATT_A   4
#define ATT_BT  5

// ---------------- helpers ---------------------------------------------------
__device__ __forceinline__ uint32_t smem_to_u32(const void* p) {
    uint32_t a;
    asm("{ .reg .u64 t; cvta.to.shared.u64 t, %1; cvt.u32.u64 %0, t; }" : "=r"(a) : "l"(p));
    return a;
}
__device__ __forceinline__ void ldsm_x4(uint32_t* r, uint32_t addr) {
    asm volatile("ldmatrix.sync.aligned.m8n8.x4.shared.b16 {%0,%1,%2,%3}, [%4];"
                 : "=r"(r[0]), "=r"(r[1]), "=r"(r[2]), "=r"(r[3]) : "r"(addr));
}
__device__ __forceinline__ void ldsm_x4_trans(uint32_t* r, uint32_t addr) {
    asm volatile("ldmatrix.sync.aligned.m8n8.x4.trans.shared.b16 {%0,%1,%2,%3}, [%4];"
                 : "=r"(r[0]), "=r"(r[1]), "=r"(r[2]), "=r"(r[3]) : "r"(addr));
}
__device__ __forceinline__ void mma16816(float* c, const uint32_t* a, const uint32_t* b) {
    asm volatile(
        "mma.sync.aligned.m16n8k16.row.col.f32.f16.f16.f32 "
        "{%0,%1,%2,%3}, {%4,%5,%6,%7}, {%8,%9}, {%0,%1,%2,%3};"
        : "+f"(c[0]), "+f"(c[1]), "+f"(c[2]), "+f"(c[3])
        : "r"(a[0]), "r"(a[1]), "r"(a[2]), "r"(a[3]), "r"(b[0]), "r"(b[1]));
}
__device__ __forceinline__ uint32_t pack2(__half a, __half b) {
    __half2 h = __halves2half2(a, b);
    return *reinterpret_cast<uint32_t*>(&h);
}

// ---------------------------------------------------------------------------
// Element-wise hi/lo fp16 split of both inputs. grid (TENS/1024, 2), block 256.
// ---------------------------------------------------------------------------
__global__ __launch_bounds__(256)
void convert_split_kernel(const float4* __restrict__ X1,
                          uint2* __restrict__ hi1, uint2* __restrict__ lo1,
                          const float4* __restrict__ X2,
                          uint2* __restrict__ hi2, uint2* __restrict__ lo2)
{
    const float4* X = blockIdx.y ? X2 : X1;
    uint2* hi = blockIdx.y ? hi2 : hi1;
    uint2* lo = blockIdx.y ? lo2 : lo1;
    size_t i = (size_t)blockIdx.x * 256 + threadIdx.x;
    float4 v = X[i];
    __half h0 = __float2half_rn(v.x), h1 = __float2half_rn(v.y);
    __half h2 = __float2half_rn(v.z), h3 = __float2half_rn(v.w);
    uint2 H, L;
    H.x = pack2(h0, h1);
    H.y = pack2(h2, h3);
    L.x = pack2(__float2half_rn(v.x - __half2float(h0)),
                __float2half_rn(v.y - __half2float(h1)));
    L.y = pack2(__float2half_rn(v.z - __half2float(h2)),
                __float2half_rn(v.w - __half2float(h3)));
    hi[i] = H;
    lo[i] = L;
}

// ---------------------------------------------------------------------------
// fp16 tensor-core GEMM (mma.sync m16n8k16), fp32 out.
// 128 threads = 4 warps in 2x2 grid, 64x64 warp tile (128 acc regs).
// NTERMS=3: BK=32, 3 stages (32KB/stage); C = Ahi*Bhi + Ahi*Blo + Alo*Bhi;
//           B K-major [n][k]; writes C + CT (CT via smem transpose, coalesced).
// NTERMS=1: BK=32, 4 stages (16KB/stage); C = A*B; B row-major [k][n] via
//           ldmatrix.x4.trans; merged dual launch.
// 2 CTAs/SM.
// ---------------------------------------------------------------------------
template<int NTERMS>
__global__ __launch_bounds__(128, 2)
void gemm_tc_kernel(const __half* __restrict__ Ahi, const __half* __restrict__ Alo,
                    const __half* __restrict__ Bhi, const __half* __restrict__ Blo,
                    float* __restrict__ C, float* __restrict__ CT,
                    const __half* __restrict__ A2, const __half* __restrict__ B2,
                    float* __restrict__ C2)
{
    constexpr int NTILES  = (NTERMS == 3) ? 4 : 2;
    constexpr int NSTAGES = (NTERMS == 3) ? 3 : 4;
    constexpr int TSZ     = 8192;
    constexpr int STSZ    = NTILES * TSZ;
    constexpr int NITER   = 16;

    extern __shared__ char smem[];
    const uint32_t sb = smem_to_u32(smem);
    const int tid = threadIdx.x;
    const int lane = tid & 31, wid = tid >> 5;
    const int wm = wid >> 1;            // 0..1 (64 rows each)
    const int wn = wid & 1;             // 0..1 (64 cols each)
    const int zb = blockIdx.z;
    const size_t boff = (size_t)(zb & (NB - 1)) * S * S;
    const int m0 = blockIdx.y * 128, n0 = blockIdx.x * 128;

    const __half *gAhi, *gAlo, *gBhi, *gBlo, *gBkn;
    float* Cout;
    if (NTERMS == 3) {
        gAhi = Ahi + boff + (size_t)m0 * S;
        gAlo = Alo + boff + (size_t)m0 * S;
        gBhi = Bhi + boff + (size_t)n0 * S;
        gBlo = Blo + boff + (size_t)n0 * S;
        Cout = C;
    } else {
        if (zb < NB) { gAhi = Ahi + boff + (size_t)m0 * S; gBkn = Bhi + boff + n0; Cout = C; }
        else         { gAhi = A2  + boff + (size_t)m0 * S; gBkn = B2  + boff + n0; Cout = C2; }
    }

    auto load_stage = [&](int st, int k0) {
        uint32_t base = sb + st * STSZ;
        if (NTERMS == 3) {
            const __half* gs[4] = {gAhi, gAlo, gBhi, gBlo};
#pragma unroll
            for (int t = 0; t < 4; t++) {
                const __half* g = gs[t] + k0;
                uint32_t tb = base + t * TSZ;
#pragma unroll
                for (int j = 0; j < 4; j++) {
                    int idx = j * 128 + tid;
                    int row = idx >> 2, c = idx & 3;
                    uint32_t dst = tb + row * 64 + ((uint32_t)(c ^ ((row >> 1) & 3)) << 4);
                    asm volatile("cp.async.cg.shared.global [%0], [%1], 16;"
                                 :: "r"(dst), "l"(g + row * S + c * 8) : "memory");
                }
            }
        } else {
            // A tile [m128][k32], 64B rows
#pragma unroll
            for (int j = 0; j < 4; j++) {
                int idx = j * 128 + tid;
                int row = idx >> 2, c = idx & 3;
                uint32_t dst = base + row * 64 + ((uint32_t)(c ^ ((row >> 1) & 3)) << 4);
                asm volatile("cp.async.cg.shared.global [%0], [%1], 16;"
                             :: "r"(dst), "l"(gAhi + row * S + k0 + c * 8) : "memory");
            }
            // B tile [k32][n128], 256B rows, row-XOR swizzle
#pragma unroll
            for (int j = 0; j < 4; j++) {
                int idx = j * 128 + tid;
                int row = idx >> 4, c = idx & 15;
                uint32_t dst = base + TSZ + row * 256 + ((uint32_t)(c ^ (row & 7)) << 4);
                asm volatile("cp.async.cg.shared.global [%0], [%1], 16;"
                             :: "r"(dst), "l"(gBkn + (size_t)(k0 + row) * S + c * 8) : "memory");
            }
        }
        asm volatile("cp.async.commit_group;" ::: "memory");
    };

    float acc[4][8][4];
#pragma unroll
    for (int i = 0; i < 4; i++)
#pragma unroll
        for (int j = 0; j < 8; j++)
#pragma unroll
            for (int q = 0; q < 4; q++) acc[i][j][q] = 0.0f;

#pragma unroll
    for (int s = 0; s < NSTAGES - 1; s++) load_stage(s, s * 32);

    for (int i = 0; i < NITER; i++) {
        if (NSTAGES == 4) asm volatile("cp.async.wait_group 2;" ::: "memory");
        else              asm volatile("cp.async.wait_group 1;" ::: "memory");
        __syncthreads();
        if (i + NSTAGES - 1 < NITER)
            load_stage((i + NSTAGES - 1) % NSTAGES, (i + NSTAGES - 1) * 32);
        else
            asm volatile("cp.async.commit_group;" ::: "memory");

        const uint32_t stb = sb + (i % NSTAGES) * STSZ;
#pragma unroll
        for (int ks = 0; ks < 2; ks++) {
            uint32_t ah[4][4], al[4][4];
#pragma unroll
            for (int mf = 0; mf < 4; mf++) {
                int row = wm * 64 + mf * 16 + (lane & 15);
                int ch = (ks * 2 + (lane >> 4)) ^ ((row >> 1) & 3);
                uint32_t off = row * 64 + (ch << 4);
                ldsm_x4(ah[mf], stb + off);
                if (NTERMS == 3) ldsm_x4(al[mf], stb + TSZ + off);
            }
#pragma unroll
            for (int nfp = 0; nfp < 4; nfp++) {      // pairs of n8 groups
                uint32_t bh[4], bl[4];
                if (NTERMS == 3) {
                    // B K-major [n][k], 64B rows: x4 = 2 n-groups x 2 k-chunks
                    int nrow = wn * 64 + nfp * 16 + ((lane >> 4) << 3) + (lane & 7);
                    int ch = (ks * 2 + ((lane >> 3) & 1)) ^ ((nrow >> 1) & 3);
                    uint32_t off = nrow * 64 + (ch << 4);
                    ldsm_x4(bh, stb + 2 * TSZ + off);
                    ldsm_x4(bl, stb + 3 * TSZ + off);
                } else {
                    // B row-major [k][n], 256B rows: x4.trans = 2 n-groups
                    int row = ks * 16 + ((lane >> 3) & 1) * 8 + (lane & 7);
                    int chunk = wn * 8 + nfp * 2 + (lane >> 4);
                    uint32_t off = row * 256 + ((uint32_t)(chunk ^ (row & 7)) << 4);
                    ldsm_x4_trans(bh, stb + TSZ + off);
                }
#pragma unroll
                for (int nn = 0; nn < 2; nn++) {
                    int nf = nfp * 2 + nn;
#pragma unroll
                    for (int mf = 0; mf < 4; mf++) {
                        mma16816(acc[mf][nf], ah[mf], bh + nn * 2);
                        if (NTERMS == 3) {
                            mma16816(acc[mf][nf], ah[mf], bl + nn * 2);
                            mma16816(acc[mf][nf], al[mf], bh + nn * 2);
                        }
                    }
                }
            }
        }
    }

    // ---- epilogue: direct C store (coalesced float2 rows) -----------------
    float* Cb = Cout + boff;
#pragma unroll
    for (int mf = 0; mf < 4; mf++) {
#pragma unroll
        for (int nf = 0; nf < 8; nf++) {
            int r  = m0 + wm * 64 + mf * 16 + (lane >> 2);
            int cc = n0 + wn * 64 + nf * 8 + (lane & 3) * 2;
            *(float2*)&Cb[(size_t)r * S + cc]       = make_float2(acc[mf][nf][0], acc[mf][nf][1]);
            *(float2*)&Cb[(size_t)(r + 8) * S + cc] = make_float2(acc[mf][nf][2], acc[mf][nf][3]);
        }
    }

    // ---- CT epilogue (NTERMS=3): transpose via smem, coalesced writes -----
    if (NTERMS == 3) {
        constexpr int PITCH = 132;                 // floats; 132*4=528B, 16B-aligned
        float* smT = (float*)smem;                 // 128*132*4 = 67.6 KB <= 96 KB
        __syncthreads();                           // pipeline smem reads all done
#pragma unroll
        for (int mf = 0; mf < 4; mf++)
#pragma unroll
            for (int nf = 0; nf < 8; nf++) {
                int rl  = wm * 64 + mf * 16 + (lane >> 2);
                int ccl = wn * 64 + nf * 8 + (lane & 3) * 2;
                smT[ccl * PITCH + rl]           = acc[mf][nf][0];
                smT[(ccl + 1) * PITCH + rl]     = acc[mf][nf][1];
                smT[ccl * PITCH + rl + 8]       = acc[mf][nf][2];
                smT[(ccl + 1) * PITCH + rl + 8] = acc[mf][nf][3];
            }
        __syncthreads();
        float* Tb = CT + boff;
#pragma unroll
        for (int r4 = 0; r4 < 8; r4++) {
            int ccl = wid * 32 + r4 * 4 + (lane >> 3);
#pragma unroll
            for (int cg = 0; cg < 4; cg++) {
                int c4 = (lane & 7) + cg * 8;
                float4 v = *(float4*)&smT[ccl * PITCH + c4 * 4];
                *(float4*)&Tb[(size_t)(n0 + ccl) * S + m0 + c4 * 4] = v;
            }
        }
    }
}

// ---------------------------------------------------------------------------
// Fused row softmax: z=0: sim rows + pre_mask -> attA [p][h]
//                    z=1: simT rows + hyp_mask -> attBT [h][p]
// One warp per row, shfl reductions. grid (S/8, NB, 2), block 256.
// ---------------------------------------------------------------------------
__global__ __launch_bounds__(256)
void softmax_fused_kernel(const int* __restrict__ pre_mask,
                          const int* __restrict__ hyp_mask,
                          __half* __restrict__ attA, __half* __restrict__ attBT)
{
    const int z = blockIdx.z;
    const float* src = z ? g_simT : g_sim;
    const int*  mask = z ? hyp_mask : pre_mask;
    __half*      dst = z ? attBT : attA;

    const int b = blockIdx.y;
    const int w = threadIdx.x >> 5, lane = threadIdx.x & 31;
    const int p = blockIdx.x * 8 + w;
    const float c = (mask[b * S + p] == 0) ? NEG_MASK : 0.0f;
    const size_t off = ((size_t)b * S + p) * S;
    const float* row = src + off;

    float4 v[4];
#pragma unroll
    for (int seg = 0; seg < 4; seg++) {
        v[seg] = *(const float4*)&row[seg * 128 + lane * 4];
        v[seg].x += c; v[seg].y += c; v[seg].z += c; v[seg].w += c;
    }

    float M = -3.0e38f;
#pragma unroll
    for (int seg = 0; seg < 4; seg++)
        M = fmaxf(M, fmaxf(fmaxf(v[seg].x, v[seg].y), fmaxf(v[seg].z, v[seg].w)));
#pragma unroll
    for (int o = 16; o > 0; o >>= 1)
        M = fmaxf(M, __shfl_xor_sync(0xFFFFFFFFu, M, o));

    float s = 0.0f;
    float4 e[4];
#pragma unroll
    for (int seg = 0; seg < 4; seg++) {
        e[seg].x = __expf(v[seg].x - M); e[seg].y = __expf(v[seg].y - M);
        e[seg].z = __expf(v[seg].z - M); e[seg].w = __expf(v[seg].w - M);
        s += e[seg].x + e[seg].y + e[seg].z + e[seg].w;
    }
#pragma unroll
    for (int o = 16; o > 0; o >>= 1)
        s += __shfl_xor_sync(0xFFFFFFFFu, s, o);
    const float inv = 1.0f / s;

#pragma unroll
    for (int seg = 0; seg < 4; seg++) {
        size_t o4 = off + seg * 128 + lane * 4;
        *(uint2*)&dst[o4] = make_uint2(
            pack2(__float2half_rn(e[seg].x * inv), __float2half_rn(e[seg].y * inv)),
            pack2(__float2half_rn(e[seg].z * inv), __float2half_rn(e[seg].w * inv)));
    }
}

// ---------------------------------------------------------------------------
extern "C" void kernel_launch(void* const* d_in, const int* in_sizes, int n_in,
                              void* d_out, int out_size)
{
    const float* premise  = (const float*)d_in[0];
    const int*   pre_mask = (const int*)  d_in[1];
    const float* hypo     = (const float*)d_in[2];
    const int*   hyp_mask = (const int*)  d_in[3];
    float* out1 = (float*)d_out;
    float* out2 = out1 + TENS;

    float *sim, *simT;
    __half* buf;
    cudaGetSymbolAddress((void**)&sim,  g_sim);
    cudaGetSymbolAddress((void**)&simT, g_simT);
    cudaGetSymbolAddress((void**)&buf,  g_buf);
    auto slot = [&](int i) { return buf + (size_t)i * TENS; };

    const int SMEM3 = 3 * 4 * 8192;   // 96 KB
    const int SMEM1 = 4 * 2 * 8192;   // 64 KB
    cudaFuncSetAttribute(gemm_tc_kernel<3>,
                         cudaFuncAttributeMaxDynamicSharedMemorySize, SMEM3);
    cudaFuncSetAttribute(gemm_tc_kernel<1>,
                         cudaFuncAttributeMaxDynamicSharedMemorySize, SMEM1);

    // 1. hi/lo fp16 splits of both inputs (element-wise, one launch)
    convert_split_kernel<<<dim3((unsigned)(TENS / 1024), 2), 256>>>(
        (const float4*)premise, (uint2*)slot(PRE_HI), (uint2*)slot(PRE_LO),
        (const float4*)hypo,    (uint2*)slot(HYP_HI), (uint2*)slot(HYP_LO));

    // 2. sim = premise @ hypothesis^T (3-term split) -> sim and simT
    gemm_tc_kernel<3><<<dim3(4, 4, NB), 128, SMEM3>>>(
        slot(PRE_HI), slot(PRE_LO), slot(HYP_HI), slot(HYP_LO), sim, simT,
        nullptr, nullptr, nullptr);

    // 3. both softmaxes in one launch -> attA [p][h], attBT [h][p]
    softmax_fused_kernel<<<dim3(S / 8, NB, 2), 256>>>(
        pre_mask, hyp_mask, slot(ATT_A), slot(ATT_BT));

    // 4+5. both attended GEMMs (BK=32, 4-stage, B row-major via ldmatrix.x4.trans)
    //      z<NB: attA @ hyp -> out1 ; z>=NB: attBT @ pre -> out2
    gemm_tc_kernel<1><<<dim3(4, 4, 2 * NB), 128, SMEM1>>>(
        slot(ATT_A), nullptr, slot(HYP_HI), nullptr, out1, nullptr,
        slot(ATT_BT), slot(PRE_HI), out2);
}

// round 13
// speedup vs baseline: 1.2088x; 1.0202x over previous
#include <cuda_runtime.h>
#include <cuda_fp16.h>
#include <cstdint>

#define NB 64
#define S  512
#define NEG_MASK -999999.0f

#define TENS ((size_t)NB * S * S)

// ---------------- scratch ---------------------------------------------------
__device__ float  g_sim [TENS];
__device__ float  g_simT[TENS];
__device__ __half g_buf[6 * TENS];

#define PRE_HI  0
#define PRE_LO  1
#define HYP_HI  2
#define HYP_LO  3
#define ATT_A   4
#define ATT_BT  5

// ---------------- helpers ---------------------------------------------------
__device__ __forceinline__ uint32_t smem_to_u32(const void* p) {
    uint32_t a;
    asm("{ .reg .u64 t; cvta.to.shared.u64 t, %1; cvt.u32.u64 %0, t; }" : "=r"(a) : "l"(p));
    return a;
}
__device__ __forceinline__ void ldsm_x4(uint32_t* r, uint32_t addr) {
    asm volatile("ldmatrix.sync.aligned.m8n8.x4.shared.b16 {%0,%1,%2,%3}, [%4];"
                 : "=r"(r[0]), "=r"(r[1]), "=r"(r[2]), "=r"(r[3]) : "r"(addr));
}
__device__ __forceinline__ void ldsm_x4_trans(uint32_t* r, uint32_t addr) {
    asm volatile("ldmatrix.sync.aligned.m8n8.x4.trans.shared.b16 {%0,%1,%2,%3}, [%4];"
                 : "=r"(r[0]), "=r"(r[1]), "=r"(r[2]), "=r"(r[3]) : "r"(addr));
}
__device__ __forceinline__ void mma16816(float* c, const uint32_t* a, const uint32_t* b) {
    asm volatile(
        "mma.sync.aligned.m16n8k16.row.col.f32.f16.f16.f32 "
        "{%0,%1,%2,%3}, {%4,%5,%6,%7}, {%8,%9}, {%0,%1,%2,%3};"
        : "+f"(c[0]), "+f"(c[1]), "+f"(c[2]), "+f"(c[3])
        : "r"(a[0]), "r"(a[1]), "r"(a[2]), "r"(a[3]), "r"(b[0]), "r"(b[1]));
}
__device__ __forceinline__ uint32_t pack2(__half a, __half b) {
    __half2 h = __halves2half2(a, b);
    return *reinterpret_cast<uint32_t*>(&h);
}

// ---------------------------------------------------------------------------
// Element-wise hi/lo fp16 split of both inputs. grid (TENS/1024, 2), block 256.
// ---------------------------------------------------------------------------
__global__ __launch_bounds__(256)
void convert_split_kernel(const float4* __restrict__ X1,
                          uint2* __restrict__ hi1, uint2* __restrict__ lo1,
                          const float4* __restrict__ X2,
                          uint2* __restrict__ hi2, uint2* __restrict__ lo2)
{
    const float4* X = blockIdx.y ? X2 : X1;
    uint2* hi = blockIdx.y ? hi2 : hi1;
    uint2* lo = blockIdx.y ? lo2 : lo1;
    size_t i = (size_t)blockIdx.x * 256 + threadIdx.x;
    float4 v = X[i];
    __half h0 = __float2half_rn(v.x), h1 = __float2half_rn(v.y);
    __half h2 = __float2half_rn(v.z), h3 = __float2half_rn(v.w);
    uint2 H, L;
    H.x = pack2(h0, h1);
    H.y = pack2(h2, h3);
    L.x = pack2(__float2half_rn(v.x - __half2float(h0)),
                __float2half_rn(v.y - __half2float(h1)));
    L.y = pack2(__float2half_rn(v.z - __half2float(h2)),
                __float2half_rn(v.w - __half2float(h3)));
    hi[i] = H;
    lo[i] = L;
}

// ---------------------------------------------------------------------------
// fp16 tensor-core GEMM (mma.sync m16n8k16), fp32 out.
// 128 threads = 4 warps in 2x2 grid.
// NTERMS=3: CTA tile 128x64 (warp tile 64x32), BK=32, 3 stages (24KB/stage);
//           C = Ahi*Bhi + Ahi*Blo + Alo*Bhi; B K-major [n][k];
//           writes C + CT (scatter). grid (8,4,NB) -> 2048 CTAs (6.92 waves).
// NTERMS=1: CTA tile 128x128 (warp tile 64x64), BK=32, 4 stages (16KB/stage);
//           C = A*B; B row-major [k][n] via ldmatrix.x4.trans; dual launch.
// 2 CTAs/SM.
// ---------------------------------------------------------------------------
template<int NTERMS>
__global__ __launch_bounds__(128, 2)
void gemm_tc_kernel(const __half* __restrict__ Ahi, const __half* __restrict__ Alo,
                    const __half* __restrict__ Bhi, const __half* __restrict__ Blo,
                    float* __restrict__ C, float* __restrict__ CT,
                    const __half* __restrict__ A2, const __half* __restrict__ B2,
                    float* __restrict__ C2)
{
    constexpr int NSTAGES = (NTERMS == 3) ? 3 : 4;
    constexpr int STSZ    = (NTERMS == 3) ? 24576 : 16384;
    constexpr int NITER   = 16;
    constexpr int BN      = (NTERMS == 3) ? 64 : 128;   // CTA n-width
    constexpr int WN      = BN / 2;                      // warp n-width
    constexpr int NNF     = WN / 8;                      // n8 frags per warp
    constexpr int NFP     = NNF / 2;                     // ldsm x4 pairs

    extern __shared__ char smem[];
    const uint32_t sb = smem_to_u32(smem);
    const int tid = threadIdx.x;
    const int lane = tid & 31, wid = tid >> 5;
    const int wm = wid >> 1;            // 0..1 (64 m-rows each)
    const int wn = wid & 1;             // 0..1 (WN n-cols each)
    const int zb = blockIdx.z;
    const size_t boff = (size_t)(zb & (NB - 1)) * S * S;
    const int m0 = blockIdx.y * 128, n0 = blockIdx.x * BN;

    const __half *gAhi, *gAlo, *gBhi, *gBlo, *gBkn;
    float* Cout;
    if (NTERMS == 3) {
        gAhi = Ahi + boff + (size_t)m0 * S;
        gAlo = Alo + boff + (size_t)m0 * S;
        gBhi = Bhi + boff + (size_t)n0 * S;
        gBlo = Blo + boff + (size_t)n0 * S;
        Cout = C;
    } else {
        if (zb < NB) { gAhi = Ahi + boff + (size_t)m0 * S; gBkn = Bhi + boff + n0; Cout = C; }
        else         { gAhi = A2  + boff + (size_t)m0 * S; gBkn = B2  + boff + n0; Cout = C2; }
    }

    auto load_stage = [&](int st, int k0) {
        uint32_t base = sb + st * STSZ;
        if (NTERMS == 3) {
            // Ahi/Alo: [128 m][32 k], 64B rows, 8KB each
#pragma unroll
            for (int t = 0; t < 2; t++) {
                const __half* g = (t == 0 ? gAhi : gAlo) + k0;
                uint32_t tb = base + t * 8192;
#pragma unroll
                for (int j = 0; j < 4; j++) {
                    int idx = j * 128 + tid;
                    int row = idx >> 2, c = idx & 3;
                    uint32_t dst = tb + row * 64 + ((uint32_t)(c ^ ((row >> 1) & 3)) << 4);
                    asm volatile("cp.async.cg.shared.global [%0], [%1], 16;"
                                 :: "r"(dst), "l"(g + row * S + c * 8) : "memory");
                }
            }
            // Bhi/Blo: [64 n][32 k], 64B rows, 4KB each
#pragma unroll
            for (int t = 0; t < 2; t++) {
                const __half* g = (t == 0 ? gBhi : gBlo) + k0;
                uint32_t tb = base + 16384 + t * 4096;
#pragma unroll
                for (int j = 0; j < 2; j++) {
                    int idx = j * 128 + tid;
                    int row = idx >> 2, c = idx & 3;
                    uint32_t dst = tb + row * 64 + ((uint32_t)(c ^ ((row >> 1) & 3)) << 4);
                    asm volatile("cp.async.cg.shared.global [%0], [%1], 16;"
                                 :: "r"(dst), "l"(g + row * S + c * 8) : "memory");
                }
            }
        } else {
            // A tile [m128][k32], 64B rows
#pragma unroll
            for (int j = 0; j < 4; j++) {
                int idx = j * 128 + tid;
                int row = idx >> 2, c = idx & 3;
                uint32_t dst = base + row * 64 + ((uint32_t)(c ^ ((row >> 1) & 3)) << 4);
                asm volatile("cp.async.cg.shared.global [%0], [%1], 16;"
                             :: "r"(dst), "l"(gAhi + row * S + k0 + c * 8) : "memory");
            }
            // B tile [k32][n128], 256B rows, row-XOR swizzle
#pragma unroll
            for (int j = 0; j < 4; j++) {
                int idx = j * 128 + tid;
                int row = idx >> 4, c = idx & 15;
                uint32_t dst = base + 8192 + row * 256 + ((uint32_t)(c ^ (row & 7)) << 4);
                asm volatile("cp.async.cg.shared.global [%0], [%1], 16;"
                             :: "r"(dst), "l"(gBkn + (size_t)(k0 + row) * S + c * 8) : "memory");
            }
        }
        asm volatile("cp.async.commit_group;" ::: "memory");
    };

    float acc[4][NNF][4];
#pragma unroll
    for (int i = 0; i < 4; i++)
#pragma unroll
        for (int j = 0; j < NNF; j++)
#pragma unroll
            for (int q = 0; q < 4; q++) acc[i][j][q] = 0.0f;

#pragma unroll
    for (int s = 0; s < NSTAGES - 1; s++) load_stage(s, s * 32);

    for (int i = 0; i < NITER; i++) {
        if (NSTAGES == 4) asm volatile("cp.async.wait_group 2;" ::: "memory");
        else              asm volatile("cp.async.wait_group 1;" ::: "memory");
        __syncthreads();
        if (i + NSTAGES - 1 < NITER)
            load_stage((i + NSTAGES - 1) % NSTAGES, (i + NSTAGES - 1) * 32);
        else
            asm volatile("cp.async.commit_group;" ::: "memory");

        const uint32_t stb = sb + (i % NSTAGES) * STSZ;
#pragma unroll
        for (int ks = 0; ks < 2; ks++) {
            uint32_t ah[4][4], al[4][4];
#pragma unroll
            for (int mf = 0; mf < 4; mf++) {
                int row = wm * 64 + mf * 16 + (lane & 15);
                int ch = (ks * 2 + (lane >> 4)) ^ ((row >> 1) & 3);
                uint32_t off = row * 64 + (ch << 4);
                ldsm_x4(ah[mf], stb + off);
                if (NTERMS == 3) ldsm_x4(al[mf], stb + 8192 + off);
            }
#pragma unroll
            for (int nfp = 0; nfp < NFP; nfp++) {      // pairs of n8 groups
                uint32_t bh[4], bl[4];
                if (NTERMS == 3) {
                    // B K-major [n][k], 64B rows: x4 = 2 n-groups x 2 k-chunks
                    int nrow = wn * WN + nfp * 16 + ((lane >> 4) << 3) + (lane & 7);
                    int ch = (ks * 2 + ((lane >> 3) & 1)) ^ ((nrow >> 1) & 3);
                    uint32_t off = nrow * 64 + (ch << 4);
                    ldsm_x4(bh, stb + 16384 + off);
                    ldsm_x4(bl, stb + 20480 + off);
                } else {
                    // B row-major [k][n], 256B rows: x4.trans = 2 n-groups
                    int row = ks * 16 + ((lane >> 3) & 1) * 8 + (lane & 7);
                    int chunk = wn * 8 + nfp * 2 + (lane >> 4);
                    uint32_t off = row * 256 + ((uint32_t)(chunk ^ (row & 7)) << 4);
                    ldsm_x4_trans(bh, stb + 8192 + off);
                }
#pragma unroll
                for (int nn = 0; nn < 2; nn++) {
                    int nf = nfp * 2 + nn;
#pragma unroll
                    for (int mf = 0; mf < 4; mf++) {
                        mma16816(acc[mf][nf], ah[mf], bh + nn * 2);
                        if (NTERMS == 3) {
                            mma16816(acc[mf][nf], ah[mf], bl + nn * 2);
                            mma16816(acc[mf][nf], al[mf], bh + nn * 2);
                        }
                    }
                }
            }
        }
    }

    // ---- epilogue: direct C store (coalesced float2 rows) + CT scatter ----
    float* Cb = Cout + boff;
#pragma unroll
    for (int mf = 0; mf < 4; mf++) {
#pragma unroll
        for (int nf = 0; nf < NNF; nf++) {
            int r  = m0 + wm * 64 + mf * 16 + (lane >> 2);
            int cc = n0 + wn * WN + nf * 8 + (lane & 3) * 2;
            *(float2*)&Cb[(size_t)r * S + cc]       = make_float2(acc[mf][nf][0], acc[mf][nf][1]);
            *(float2*)&Cb[(size_t)(r + 8) * S + cc] = make_float2(acc[mf][nf][2], acc[mf][nf][3]);
            if (NTERMS == 3) {
                float* Tb = CT + boff;
                Tb[(size_t)cc * S + r]           = acc[mf][nf][0];
                Tb[(size_t)(cc + 1) * S + r]     = acc[mf][nf][1];
                Tb[(size_t)cc * S + r + 8]       = acc[mf][nf][2];
                Tb[(size_t)(cc + 1) * S + r + 8] = acc[mf][nf][3];
            }
        }
    }
}

// ---------------------------------------------------------------------------
// Fused row softmax: z=0: sim rows + pre_mask -> attA [p][h]
//                    z=1: simT rows + hyp_mask -> attBT [h][p]
// One warp per row, shfl reductions. grid (S/8, NB, 2), block 256.
// ---------------------------------------------------------------------------
__global__ __launch_bounds__(256)
void softmax_fused_kernel(const int* __restrict__ pre_mask,
                          const int* __restrict__ hyp_mask,
                          __half* __restrict__ attA, __half* __restrict__ attBT)
{
    const int z = blockIdx.z;
    const float* src = z ? g_simT : g_sim;
    const int*  mask = z ? hyp_mask : pre_mask;
    __half*      dst = z ? attBT : attA;

    const int b = blockIdx.y;
    const int w = threadIdx.x >> 5, lane = threadIdx.x & 31;
    const int p = blockIdx.x * 8 + w;
    const float c = (mask[b * S + p] == 0) ? NEG_MASK : 0.0f;
    const size_t off = ((size_t)b * S + p) * S;
    const float* row = src + off;

    float4 v[4];
#pragma unroll
    for (int seg = 0; seg < 4; seg++) {
        v[seg] = *(const float4*)&row[seg * 128 + lane * 4];
        v[seg].x += c; v[seg].y += c; v[seg].z += c; v[seg].w += c;
    }

    float M = -3.0e38f;
#pragma unroll
    for (int seg = 0; seg < 4; seg++)
        M = fmaxf(M, fmaxf(fmaxf(v[seg].x, v[seg].y), fmaxf(v[seg].z, v[seg].w)));
#pragma unroll
    for (int o = 16; o > 0; o >>= 1)
        M = fmaxf(M, __shfl_xor_sync(0xFFFFFFFFu, M, o));

    float s = 0.0f;
    float4 e[4];
#pragma unroll
    for (int seg = 0; seg < 4; seg++) {
        e[seg].x = __expf(v[seg].x - M); e[seg].y = __expf(v[seg].y - M);
        e[seg].z = __expf(v[seg].z - M); e[seg].w = __expf(v[seg].w - M);
        s += e[seg].x + e[seg].y + e[seg].z + e[seg].w;
    }
#pragma unroll
    for (int o = 16; o > 0; o >>= 1)
        s += __shfl_xor_sync(0xFFFFFFFFu, s, o);
    const float inv = 1.0f / s;

#pragma unroll
    for (int seg = 0; seg < 4; seg++) {
        size_t o4 = off + seg * 128 + lane * 4;
        *(uint2*)&dst[o4] = make_uint2(
            pack2(__float2half_rn(e[seg].x * inv), __float2half_rn(e[seg].y * inv)),
            pack2(__float2half_rn(e[seg].z * inv), __float2half_rn(e[seg].w * inv)));
    }
}

// ---------------------------------------------------------------------------
extern "C" void kernel_launch(void* const* d_in, const int* in_sizes, int n_in,
                              void* d_out, int out_size)
{
    const float* premise  = (const float*)d_in[0];
    const int*   pre_mask = (const int*)  d_in[1];
    const float* hypo     = (const float*)d_in[2];
    const int*   hyp_mask = (const int*)  d_in[3];
    float* out1 = (float*)d_out;
    float* out2 = out1 + TENS;

    float *sim, *simT;
    __half* buf;
    cudaGetSymbolAddress((void**)&sim,  g_sim);
    cudaGetSymbolAddress((void**)&simT, g_simT);
    cudaGetSymbolAddress((void**)&buf,  g_buf);
    auto slot = [&](int i) { return buf + (size_t)i * TENS; };

    const int SMEM3 = 3 * 24576;   // 72 KB
    const int SMEM1 = 4 * 16384;   // 64 KB
    cudaFuncSetAttribute(gemm_tc_kernel<3>,
                         cudaFuncAttributeMaxDynamicSharedMemorySize, SMEM3);
    cudaFuncSetAttribute(gemm_tc_kernel<1>,
                         cudaFuncAttributeMaxDynamicSharedMemorySize, SMEM1);

    // 1. hi/lo fp16 splits of both inputs (element-wise, one launch)
    convert_split_kernel<<<dim3((unsigned)(TENS / 1024), 2), 256>>>(
        (const float4*)premise, (uint2*)slot(PRE_HI), (uint2*)slot(PRE_LO),
        (const float4*)hypo,    (uint2*)slot(HYP_HI), (uint2*)slot(HYP_LO));

    // 2. sim = premise @ hypothesis^T (3-term split) -> sim and simT
    //    128x64 tiles: grid 2048 CTAs = 6.92 waves (tail fix)
    gemm_tc_kernel<3><<<dim3(8, 4, NB), 128, SMEM3>>>(
        slot(PRE_HI), slot(PRE_LO), slot(HYP_HI), slot(HYP_LO), sim, simT,
        nullptr, nullptr, nullptr);

    // 3. both softmaxes in one launch -> attA [p][h], attBT [h][p]
    softmax_fused_kernel<<<dim3(S / 8, NB, 2), 256>>>(
        pre_mask, hyp_mask, slot(ATT_A), slot(ATT_BT));

    // 4+5. both attended GEMMs (BK=32, 4-stage, B row-major via ldmatrix.x4.trans)
    //      z<NB: attA @ hyp -> out1 ; z>=NB: attBT @ pre -> out2
    gemm_tc_kernel<1><<<dim3(4, 4, 2 * NB), 128, SMEM1>>>(
        slot(ATT_A), nullptr, slot(HYP_HI), nullptr, out1, nullptr,
        slot(ATT_BT), slot(PRE_HI), out2);
}

// round 14
// speedup vs baseline: 1.2346x; 1.0214x over previous
#include <cuda_runtime.h>
#include <cuda_fp16.h>
#include <cstdint>

#define NB 64
#define NBH 32                    // batches per pipeline chunk
#define S  512
#define NEG_MASK -999999.0f

#define TENS ((size_t)NB * S * S)
#define HALF_ELEMS (TENS / 2)

// ---------------- scratch ---------------------------------------------------
__device__ float  g_sim [TENS];
__device__ float  g_simT[TENS];
__device__ __half g_buf[6 * TENS];

#define PRE_HI  0
#define PRE_LO  1
#define HYP_HI  2
#define HYP_LO  3
#define ATT_A   4
#define ATT_BT  5

// ---------------- helpers ---------------------------------------------------
__device__ __forceinline__ uint32_t smem_to_u32(const void* p) {
    uint32_t a;
    asm("{ .reg .u64 t; cvta.to.shared.u64 t, %1; cvt.u32.u64 %0, t; }" : "=r"(a) : "l"(p));
    return a;
}
__device__ __forceinline__ void ldsm_x4(uint32_t* r, uint32_t addr) {
    asm volatile("ldmatrix.sync.aligned.m8n8.x4.shared.b16 {%0,%1,%2,%3}, [%4];"
                 : "=r"(r[0]), "=r"(r[1]), "=r"(r[2]), "=r"(r[3]) : "r"(addr));
}
__device__ __forceinline__ void ldsm_x4_trans(uint32_t* r, uint32_t addr) {
    asm volatile("ldmatrix.sync.aligned.m8n8.x4.trans.shared.b16 {%0,%1,%2,%3}, [%4];"
                 : "=r"(r[0]), "=r"(r[1]), "=r"(r[2]), "=r"(r[3]) : "r"(addr));
}
__device__ __forceinline__ void mma16816(float* c, const uint32_t* a, const uint32_t* b) {
    asm volatile(
        "mma.sync.aligned.m16n8k16.row.col.f32.f16.f16.f32 "
        "{%0,%1,%2,%3}, {%4,%5,%6,%7}, {%8,%9}, {%0,%1,%2,%3};"
        : "+f"(c[0]), "+f"(c[1]), "+f"(c[2]), "+f"(c[3])
        : "r"(a[0]), "r"(a[1]), "r"(a[2]), "r"(a[3]), "r"(b[0]), "r"(b[1]));
}
__device__ __forceinline__ uint32_t pack2(__half a, __half b) {
    __half2 h = __halves2half2(a, b);
    return *reinterpret_cast<uint32_t*>(&h);
}

// ---------------------------------------------------------------------------
// Element-wise hi/lo fp16 split of both inputs (one batch chunk).
// grid (HALF_ELEMS/1024, 2), block 256.
// ---------------------------------------------------------------------------
__global__ __launch_bounds__(256)
void convert_split_kernel(const float4* __restrict__ X1,
                          uint2* __restrict__ hi1, uint2* __restrict__ lo1,
                          const float4* __restrict__ X2,
                          uint2* __restrict__ hi2, uint2* __restrict__ lo2)
{
    const float4* X = blockIdx.y ? X2 : X1;
    uint2* hi = blockIdx.y ? hi2 : hi1;
    uint2* lo = blockIdx.y ? lo2 : lo1;
    size_t i = (size_t)blockIdx.x * 256 + threadIdx.x;
    float4 v = X[i];
    __half h0 = __float2half_rn(v.x), h1 = __float2half_rn(v.y);
    __half h2 = __float2half_rn(v.z), h3 = __float2half_rn(v.w);
    uint2 H, L;
    H.x = pack2(h0, h1);
    H.y = pack2(h2, h3);
    L.x = pack2(__float2half_rn(v.x - __half2float(h0)),
                __float2half_rn(v.y - __half2float(h1)));
    L.y = pack2(__float2half_rn(v.z - __half2float(h2)),
                __float2half_rn(v.w - __half2float(h3)));
    hi[i] = H;
    lo[i] = L;
}

// ---------------------------------------------------------------------------
// fp16 tensor-core GEMM (mma.sync m16n8k16), fp32 out.
// 128 threads = 4 warps in 2x2 grid. nbc = batches per chunk.
// NTERMS=3: CTA tile 128x64, BK=32, 3 stages (24KB/stage);
//           C = Ahi*Bhi + Ahi*Blo + Alo*Bhi; B K-major [n][k];
//           writes C + CT (scatter). grid (8,4,nbc).
// NTERMS=1: CTA tile 128x128, BK=32, 4 stages (16KB/stage); C = A*B;
//           B row-major [k][n] via ldmatrix.x4.trans; dual launch
//           (zb<nbc -> set1, else set2). grid (4,4,2*nbc).
// 2 CTAs/SM.
// ---------------------------------------------------------------------------
template<int NTERMS>
__global__ __launch_bounds__(128, 2)
void gemm_tc_kernel(const __half* __restrict__ Ahi, const __half* __restrict__ Alo,
                    const __half* __restrict__ Bhi, const __half* __restrict__ Blo,
                    float* __restrict__ C, float* __restrict__ CT,
                    const __half* __restrict__ A2, const __half* __restrict__ B2,
                    float* __restrict__ C2, int nbc)
{
    constexpr int NSTAGES = (NTERMS == 3) ? 3 : 4;
    constexpr int STSZ    = (NTERMS == 3) ? 24576 : 16384;
    constexpr int NITER   = 16;
    constexpr int BN      = (NTERMS == 3) ? 64 : 128;   // CTA n-width
    constexpr int WN      = BN / 2;                      // warp n-width
    constexpr int NNF     = WN / 8;                      // n8 frags per warp
    constexpr int NFP     = NNF / 2;                     // ldsm x4 pairs

    extern __shared__ char smem[];
    const uint32_t sb = smem_to_u32(smem);
    const int tid = threadIdx.x;
    const int lane = tid & 31, wid = tid >> 5;
    const int wm = wid >> 1;            // 0..1 (64 m-rows each)
    const int wn = wid & 1;             // 0..1 (WN n-cols each)
    const int zb = blockIdx.z;
    const int bloc = (zb < nbc) ? zb : zb - nbc;
    const size_t boff = (size_t)bloc * S * S;
    const int m0 = blockIdx.y * 128, n0 = blockIdx.x * BN;

    const __half *gAhi, *gAlo, *gBhi, *gBlo, *gBkn;
    float* Cout;
    if (NTERMS == 3) {
        gAhi = Ahi + boff + (size_t)m0 * S;
        gAlo = Alo + boff + (size_t)m0 * S;
        gBhi = Bhi + boff + (size_t)n0 * S;
        gBlo = Blo + boff + (size_t)n0 * S;
        Cout = C;
    } else {
        if (zb < nbc) { gAhi = Ahi + boff + (size_t)m0 * S; gBkn = Bhi + boff + n0; Cout = C; }
        else          { gAhi = A2  + boff + (size_t)m0 * S; gBkn = B2  + boff + n0; Cout = C2; }
    }

    auto load_stage = [&](int st, int k0) {
        uint32_t base = sb + st * STSZ;
        if (NTERMS == 3) {
            // Ahi/Alo: [128 m][32 k], 64B rows, 8KB each
#pragma unroll
            for (int t = 0; t < 2; t++) {
                const __half* g = (t == 0 ? gAhi : gAlo) + k0;
                uint32_t tb = base + t * 8192;
#pragma unroll
                for (int j = 0; j < 4; j++) {
                    int idx = j * 128 + tid;
                    int row = idx >> 2, c = idx & 3;
                    uint32_t dst = tb + row * 64 + ((uint32_t)(c ^ ((row >> 1) & 3)) << 4);
                    asm volatile("cp.async.cg.shared.global [%0], [%1], 16;"
                                 :: "r"(dst), "l"(g + row * S + c * 8) : "memory");
                }
            }
            // Bhi/Blo: [64 n][32 k], 64B rows, 4KB each
#pragma unroll
            for (int t = 0; t < 2; t++) {
                const __half* g = (t == 0 ? gBhi : gBlo) + k0;
                uint32_t tb = base + 16384 + t * 4096;
#pragma unroll
                for (int j = 0; j < 2; j++) {
                    int idx = j * 128 + tid;
                    int row = idx >> 2, c = idx & 3;
                    uint32_t dst = tb + row * 64 + ((uint32_t)(c ^ ((row >> 1) & 3)) << 4);
                    asm volatile("cp.async.cg.shared.global [%0], [%1], 16;"
                                 :: "r"(dst), "l"(g + row * S + c * 8) : "memory");
                }
            }
        } else {
            // A tile [m128][k32], 64B rows
#pragma unroll
            for (int j = 0; j < 4; j++) {
                int idx = j * 128 + tid;
                int row = idx >> 2, c = idx & 3;
                uint32_t dst = base + row * 64 + ((uint32_t)(c ^ ((row >> 1) & 3)) << 4);
                asm volatile("cp.async.cg.shared.global [%0], [%1], 16;"
                             :: "r"(dst), "l"(gAhi + row * S + k0 + c * 8) : "memory");
            }
            // B tile [k32][n128], 256B rows, row-XOR swizzle
#pragma unroll
            for (int j = 0; j < 4; j++) {
                int idx = j * 128 + tid;
                int row = idx >> 4, c = idx & 15;
                uint32_t dst = base + 8192 + row * 256 + ((uint32_t)(c ^ (row & 7)) << 4);
                asm volatile("cp.async.cg.shared.global [%0], [%1], 16;"
                             :: "r"(dst), "l"(gBkn + (size_t)(k0 + row) * S + c * 8) : "memory");
            }
        }
        asm volatile("cp.async.commit_group;" ::: "memory");
    };

    float acc[4][NNF][4];
#pragma unroll
    for (int i = 0; i < 4; i++)
#pragma unroll
        for (int j = 0; j < NNF; j++)
#pragma unroll
            for (int q = 0; q < 4; q++) acc[i][j][q] = 0.0f;

#pragma unroll
    for (int s = 0; s < NSTAGES - 1; s++) load_stage(s, s * 32);

    for (int i = 0; i < NITER; i++) {
        if (NSTAGES == 4) asm volatile("cp.async.wait_group 2;" ::: "memory");
        else              asm volatile("cp.async.wait_group 1;" ::: "memory");
        __syncthreads();
        if (i + NSTAGES - 1 < NITER)
            load_stage((i + NSTAGES - 1) % NSTAGES, (i + NSTAGES - 1) * 32);
        else
            asm volatile("cp.async.commit_group;" ::: "memory");

        const uint32_t stb = sb + (i % NSTAGES) * STSZ;
#pragma unroll
        for (int ks = 0; ks < 2; ks++) {
            uint32_t ah[4][4], al[4][4];
#pragma unroll
            for (int mf = 0; mf < 4; mf++) {
                int row = wm * 64 + mf * 16 + (lane & 15);
                int ch = (ks * 2 + (lane >> 4)) ^ ((row >> 1) & 3);
                uint32_t off = row * 64 + (ch << 4);
                ldsm_x4(ah[mf], stb + off);
                if (NTERMS == 3) ldsm_x4(al[mf], stb + 8192 + off);
            }
#pragma unroll
            for (int nfp = 0; nfp < NFP; nfp++) {      // pairs of n8 groups
                uint32_t bh[4], bl[4];
                if (NTERMS == 3) {
                    // B K-major [n][k], 64B rows: x4 = 2 n-groups x 2 k-chunks
                    int nrow = wn * WN + nfp * 16 + ((lane >> 4) << 3) + (lane & 7);
                    int ch = (ks * 2 + ((lane >> 3) & 1)) ^ ((nrow >> 1) & 3);
                    uint32_t off = nrow * 64 + (ch << 4);
                    ldsm_x4(bh, stb + 16384 + off);
                    ldsm_x4(bl, stb + 20480 + off);
                } else {
                    // B row-major [k][n], 256B rows: x4.trans = 2 n-groups
                    int row = ks * 16 + ((lane >> 3) & 1) * 8 + (lane & 7);
                    int chunk = wn * 8 + nfp * 2 + (lane >> 4);
                    uint32_t off = row * 256 + ((uint32_t)(chunk ^ (row & 7)) << 4);
                    ldsm_x4_trans(bh, stb + 8192 + off);
                }
#pragma unroll
                for (int nn = 0; nn < 2; nn++) {
                    int nf = nfp * 2 + nn;
#pragma unroll
                    for (int mf = 0; mf < 4; mf++) {
                        mma16816(acc[mf][nf], ah[mf], bh + nn * 2);
                        if (NTERMS == 3) {
                            mma16816(acc[mf][nf], ah[mf], bl + nn * 2);
                            mma16816(acc[mf][nf], al[mf], bh + nn * 2);
                        }
                    }
                }
            }
        }
    }

    // ---- epilogue: direct C store (coalesced float2 rows) + CT scatter ----
    float* Cb = Cout + boff;
#pragma unroll
    for (int mf = 0; mf < 4; mf++) {
#pragma unroll
        for (int nf = 0; nf < NNF; nf++) {
            int r  = m0 + wm * 64 + mf * 16 + (lane >> 2);
            int cc = n0 + wn * WN + nf * 8 + (lane & 3) * 2;
            *(float2*)&Cb[(size_t)r * S + cc]       = make_float2(acc[mf][nf][0], acc[mf][nf][1]);
            *(float2*)&Cb[(size_t)(r + 8) * S + cc] = make_float2(acc[mf][nf][2], acc[mf][nf][3]);
            if (NTERMS == 3) {
                float* Tb = CT + boff;
                Tb[(size_t)cc * S + r]           = acc[mf][nf][0];
                Tb[(size_t)(cc + 1) * S + r]     = acc[mf][nf][1];
                Tb[(size_t)cc * S + r + 8]       = acc[mf][nf][2];
                Tb[(size_t)(cc + 1) * S + r + 8] = acc[mf][nf][3];
            }
        }
    }
}

// ---------------------------------------------------------------------------
// Fused row softmax (one batch chunk):
//   z=0: sim rows + pre_mask -> attA [p][h]
//   z=1: simT rows + hyp_mask -> attBT [h][p]
// One warp per row, shfl reductions. grid (S/8, nbc, 2), block 256.
// ---------------------------------------------------------------------------
__global__ __launch_bounds__(256)
void softmax_fused_kernel(const float* __restrict__ sim,
                          const float* __restrict__ simT,
                          const int* __restrict__ pre_mask,
                          const int* __restrict__ hyp_mask,
                          __half* __restrict__ attA, __half* __restrict__ attBT)
{
    const int z = blockIdx.z;
    const float* src = z ? simT : sim;
    const int*  mask = z ? hyp_mask : pre_mask;
    __half*      dst = z ? attBT : attA;

    const int b = blockIdx.y;
    const int w = threadIdx.x >> 5, lane = threadIdx.x & 31;
    const int p = blockIdx.x * 8 + w;
    const float c = (mask[b * S + p] == 0) ? NEG_MASK : 0.0f;
    const size_t off = ((size_t)b * S + p) * S;
    const float* row = src + off;

    float4 v[4];
#pragma unroll
    for (int seg = 0; seg < 4; seg++) {
        v[seg] = *(const float4*)&row[seg * 128 + lane * 4];
        v[seg].x += c; v[seg].y += c; v[seg].z += c; v[seg].w += c;
    }

    float M = -3.0e38f;
#pragma unroll
    for (int seg = 0; seg < 4; seg++)
        M = fmaxf(M, fmaxf(fmaxf(v[seg].x, v[seg].y), fmaxf(v[seg].z, v[seg].w)));
#pragma unroll
    for (int o = 16; o > 0; o >>= 1)
        M = fmaxf(M, __shfl_xor_sync(0xFFFFFFFFu, M, o));

    float s = 0.0f;
    float4 e[4];
#pragma unroll
    for (int seg = 0; seg < 4; seg++) {
        e[seg].x = __expf(v[seg].x - M); e[seg].y = __expf(v[seg].y - M);
        e[seg].z = __expf(v[seg].z - M); e[seg].w = __expf(v[seg].w - M);
        s += e[seg].x + e[seg].y + e[seg].z + e[seg].w;
    }
#pragma unroll
    for (int o = 16; o > 0; o >>= 1)
        s += __shfl_xor_sync(0xFFFFFFFFu, s, o);
    const float inv = 1.0f / s;

#pragma unroll
    for (int seg = 0; seg < 4; seg++) {
        size_t o4 = off + seg * 128 + lane * 4;
        *(uint2*)&dst[o4] = make_uint2(
            pack2(__float2half_rn(e[seg].x * inv), __float2half_rn(e[seg].y * inv)),
            pack2(__float2half_rn(e[seg].z * inv), __float2half_rn(e[seg].w * inv)));
    }
}

// ---------------------------------------------------------------------------
extern "C" void kernel_launch(void* const* d_in, const int* in_sizes, int n_in,
                              void* d_out, int out_size)
{
    const float* premise  = (const float*)d_in[0];
    const int*   pre_mask = (const int*)  d_in[1];
    const float* hypo     = (const float*)d_in[2];
    const int*   hyp_mask = (const int*)  d_in[3];
    float* out1 = (float*)d_out;
    float* out2 = out1 + TENS;

    float *sim, *simT;
    __half* buf;
    cudaGetSymbolAddress((void**)&sim,  g_sim);
    cudaGetSymbolAddress((void**)&simT, g_simT);
    cudaGetSymbolAddress((void**)&buf,  g_buf);
    auto slot = [&](int i) { return buf + (size_t)i * TENS; };

    const int SMEM3 = 3 * 24576;   // 72 KB
    const int SMEM1 = 4 * 16384;   // 64 KB
    cudaFuncSetAttribute(gemm_tc_kernel<3>,
                         cudaFuncAttributeMaxDynamicSharedMemorySize, SMEM3);
    cudaFuncSetAttribute(gemm_tc_kernel<1>,
                         cudaFuncAttributeMaxDynamicSharedMemorySize, SMEM1);

    // second stream, forked from the capture-origin (default) stream
    cudaStream_t s2;
    cudaStreamCreateWithFlags(&s2, cudaStreamNonBlocking);
    cudaEvent_t evFork, evJoin;
    cudaEventCreateWithFlags(&evFork, cudaEventDisableTiming);
    cudaEventCreateWithFlags(&evJoin, cudaEventDisableTiming);
    cudaEventRecord(evFork, 0);
    cudaStreamWaitEvent(s2, evFork, 0);

    // per-chunk pipelines: chunk 0 = batches [0,32) on stream 0,
    //                      chunk 1 = batches [32,64) on s2.
    for (int ck = 0; ck < 2; ck++) {
        cudaStream_t st = ck ? s2 : (cudaStream_t)0;
        const size_t eoff = (size_t)ck * HALF_ELEMS;        // element offset
        const size_t moff = (size_t)ck * NBH * S;           // mask offset

        // 1. hi/lo fp16 splits of both inputs (this chunk)
        convert_split_kernel<<<dim3((unsigned)(HALF_ELEMS / 1024), 2), 256, 0, st>>>(
            (const float4*)(premise + eoff),
            (uint2*)(slot(PRE_HI) + eoff), (uint2*)(slot(PRE_LO) + eoff),
            (const float4*)(hypo + eoff),
            (uint2*)(slot(HYP_HI) + eoff), (uint2*)(slot(HYP_LO) + eoff));

        // 2. sim = premise @ hypothesis^T (3-term split) -> sim and simT
        gemm_tc_kernel<3><<<dim3(8, 4, NBH), 128, SMEM3, st>>>(
            slot(PRE_HI) + eoff, slot(PRE_LO) + eoff,
            slot(HYP_HI) + eoff, slot(HYP_LO) + eoff,
            sim + eoff, simT + eoff, nullptr, nullptr, nullptr, NBH);

        // 3. both softmaxes -> attA [p][h], attBT [h][p]
        softmax_fused_kernel<<<dim3(S / 8, NBH, 2), 256, 0, st>>>(
            sim + eoff, simT + eoff, pre_mask + moff, hyp_mask + moff,
            slot(ATT_A) + eoff, slot(ATT_BT) + eoff);

        // 4+5. both attended GEMMs (dual launch: z<NBH -> out1, else out2)
        gemm_tc_kernel<1><<<dim3(4, 4, 2 * NBH), 128, SMEM1, st>>>(
            slot(ATT_A) + eoff, nullptr, slot(HYP_HI) + eoff, nullptr,
            out1 + eoff, nullptr,
            slot(ATT_BT) + eoff, slot(PRE_HI) + eoff, out2 + eoff, NBH);
    }

    // join s2 back into the origin stream
    cudaEventRecord(evJoin, s2);
    cudaStreamWaitEvent((cudaStream_t)0, evJoin, 0);
}